// round 15
// baseline (speedup 1.0000x reference)
#include <cuda_runtime.h>
#include <cuda_bf16.h>
#include <cstdint>
#include <math.h>

#define B_   16
#define T_   512
#define C_   1024
#define H_   16
#define D_   64
#define M_   (B_ * T_)      // 8192
#define K_   C_             // 1024

// ---------------- scratch (no allocations allowed) ----------------
__device__ __nv_bfloat16 gx_hi[M_ * K_];
__device__ __nv_bfloat16 gx_lo[M_ * K_];
__device__ __nv_bfloat16 gw_hi[4 * C_ * C_];   // q,k,v,o
__device__ __nv_bfloat16 gw_lo[4 * C_ * C_];
__device__ __nv_bfloat16 gq_hi[M_ * C_];       // (B,H,T,D)
__device__ __nv_bfloat16 gq_lo[M_ * C_];
__device__ __nv_bfloat16 gk_hi[M_ * C_];
__device__ __nv_bfloat16 gk_lo[M_ * C_];
__device__ __nv_bfloat16 gv_hi[M_ * C_];
__device__ __nv_bfloat16 gv_lo[M_ * C_];
__device__ __nv_bfloat16 ga_hi[M_ * C_];       // (B,T,C) attn out
__device__ __nv_bfloat16 ga_lo[M_ * C_];

// ================= helpers =================
__device__ __forceinline__ uint32_t smem_u32(const void* p) {
    return (uint32_t)__cvta_generic_to_shared(p);
}

#define CP_ASYNC16(dst, src) \
    asm volatile("cp.async.cg.shared.global [%0], [%1], 16;" :: "r"(dst), "l"(src) : "memory")
#define CP_COMMIT() asm volatile("cp.async.commit_group;" ::: "memory")

#define LDMX4(r, addr) \
    asm volatile("ldmatrix.sync.aligned.m8n8.x4.shared.b16 {%0,%1,%2,%3}, [%4];" \
        : "=r"((r)[0]), "=r"((r)[1]), "=r"((r)[2]), "=r"((r)[3]) : "r"(addr))

#define LDMX4T(r, addr) \
    asm volatile("ldmatrix.sync.aligned.m8n8.x4.trans.shared.b16 {%0,%1,%2,%3}, [%4];" \
        : "=r"((r)[0]), "=r"((r)[1]), "=r"((r)[2]), "=r"((r)[3]) : "r"(addr))

#define MMA16816(d, a, b) \
    asm volatile("mma.sync.aligned.m16n8k16.row.col.f32.bf16.bf16.f32 " \
        "{%0,%1,%2,%3}, {%4,%5,%6,%7}, {%8,%9}, {%0,%1,%2,%3};" \
        : "+f"((d)[0]), "+f"((d)[1]), "+f"((d)[2]), "+f"((d)[3]) \
        : "r"((a)[0]), "r"((a)[1]), "r"((a)[2]), "r"((a)[3]), \
          "r"((b)[0]), "r"((b)[1]))

__device__ __forceinline__ void bsplit(float x, __nv_bfloat16& h, __nv_bfloat16& l) {
    h = __float2bfloat16(x);
    l = __float2bfloat16(x - __bfloat162float(h));
}
__device__ __forceinline__ uint32_t packb2(__nv_bfloat16 a, __nv_bfloat16 b) {
    __nv_bfloat162 t(a, b);
    return *(uint32_t*)&t;
}

// =================================================================
// split: fp32 -> (hi bf16, lo bf16), vectorized x4
// =================================================================
__device__ __forceinline__ void do_split(
    const float* __restrict__ in, __nv_bfloat16* __restrict__ hi,
    __nv_bfloat16* __restrict__ lo, int i)
{
    float4 v = ((const float4*)in)[i];
    __nv_bfloat16 h0, h1, h2, h3, l0, l1, l2, l3;
    bsplit(v.x, h0, l0); bsplit(v.y, h1, l1);
    bsplit(v.z, h2, l2); bsplit(v.w, h3, l3);
    ((__nv_bfloat162*)hi)[2 * i + 0] = __nv_bfloat162(h0, h1);
    ((__nv_bfloat162*)hi)[2 * i + 1] = __nv_bfloat162(h2, h3);
    ((__nv_bfloat162*)lo)[2 * i + 0] = __nv_bfloat162(l0, l1);
    ((__nv_bfloat162*)lo)[2 * i + 1] = __nv_bfloat162(l2, l3);
}

__global__ __launch_bounds__(256) void split_kernel(
    const float* __restrict__ in, __nv_bfloat16* __restrict__ hi,
    __nv_bfloat16* __restrict__ lo)
{
    do_split(in, hi, lo, blockIdx.x * blockDim.x + threadIdx.x);
}

__global__ __launch_bounds__(256) void split_w_kernel(
    const float* __restrict__ w0, const float* __restrict__ w1,
    const float* __restrict__ w2, const float* __restrict__ w3,
    __nv_bfloat16* __restrict__ hi, __nv_bfloat16* __restrict__ lo)
{
    const int wsel = blockIdx.y;
    const float* in = (wsel == 0) ? w0 : (wsel == 1) ? w1 : (wsel == 2) ? w2 : w3;
    const int WW = C_ * C_;
    do_split(in, hi + wsel * WW, lo + wsel * WW,
             blockIdx.x * blockDim.x + threadIdx.x);
}

// =================================================================
// mma.sync bf16x3 GEMM v4: CTA 128x128, 4 warps (64x64 warp tile),
// 2-stage cp.async, 2 CTAs/SM, register-level fragment pipelining.
// =================================================================
#define NITER    32               // K / 32
#define TPITCH   80               // bytes per 32-bf16 row (64 + 16 pad)
#define GT_B     (128 * TPITCH)   // 10240 (one tile: 128 rows)
#define STAGE_B  (4 * GT_B)       // Ahi,Alo,Bhi,Blo = 40960
#define GEMM_SMEM (2 * STAGE_B)   // 81920 -> 2 CTAs/SM

template<int SCATTER>
__global__ __launch_bounds__(128, 2) void gemm_big(
    const __nv_bfloat16* __restrict__ Ahi, const __nv_bfloat16* __restrict__ Alo,
    const __nv_bfloat16* __restrict__ Whi, const __nv_bfloat16* __restrict__ Wlo,
    const float* __restrict__ b0, const float* __restrict__ b1,
    const float* __restrict__ b2, float* __restrict__ out,
    __nv_bfloat16* __restrict__ oh0, __nv_bfloat16* __restrict__ ol0,
    __nv_bfloat16* __restrict__ oh1, __nv_bfloat16* __restrict__ ol1,
    __nv_bfloat16* __restrict__ oh2, __nv_bfloat16* __restrict__ ol2)
{
    extern __shared__ char smem[];
    const uint32_t sb = smem_u32(smem);
    const int tid  = threadIdx.x;
    const int lane = tid & 31;
    const int warp = tid >> 5;          // 0..3
    const int m0 = blockIdx.y * 128;
    const int n0 = blockIdx.x * 128;
    const int wm = (warp & 1) * 64;
    const int wn = (warp >> 1) * 64;

    const int z = SCATTER ? blockIdx.z : 0;
    const long WW = (long)C_ * C_;
    const __nv_bfloat16* Bh = Whi + z * WW;
    const __nv_bfloat16* Bl = Wlo + z * WW;
    const float* bias = (z == 0) ? b0 : (z == 1) ? b1 : b2;
    __nv_bfloat16* outhi = (z == 0) ? oh0 : (z == 1) ? oh1 : oh2;
    __nv_bfloat16* outlo = (z == 0) ? ol0 : (z == 1) ? ol1 : ol2;

    const __nv_bfloat16* bases[4] = {
        Ahi + (long)m0 * K_, Alo + (long)m0 * K_,
        Bh + (long)n0 * K_, Bl + (long)n0 * K_ };

    auto load_stage = [&](int it, int s) {
        const int k0 = it * 32;
        const uint32_t sdst = sb + s * STAGE_B;
#pragma unroll
        for (int j = 0; j < 16; j++) {
            const int idx = tid + j * 128;
            const int tile = idx >> 9;
            const int pos = idx & 511;
            const int row = pos >> 2;
            const int ch  = pos & 3;
            const __nv_bfloat16* src = bases[tile] + (long)row * K_ + k0 + ch * 8;
            CP_ASYNC16(sdst + tile * GT_B + row * TPITCH + ch * 16, src);
        }
        CP_COMMIT();
    };

    float acc[4][8][4];
#pragma unroll
    for (int mi = 0; mi < 4; mi++)
#pragma unroll
        for (int ni = 0; ni < 8; ni++)
#pragma unroll
            for (int r = 0; r < 4; r++) acc[mi][ni][r] = 0.0f;

    load_stage(0, 0);

    const int a_row = lane & 15;
    const int a_kb  = (lane >> 4) * 16;
    const int b_row = (lane & 7) + ((lane >> 4) << 3);
    const int b_kb  = ((lane >> 3) & 1) * 16;

    // register fragment double-buffers
    uint32_t ah[2][4][4], al[2][4][4];   // [kkbuf][mi][reg]
    uint32_t bhf[2][4], blf[2][4];       // [stepbuf][reg]; frag nn = regs 2nn,2nn+1

    for (int it = 0; it < NITER; it++) {
        if (it + 1 < NITER) {
            load_stage(it + 1, (it + 1) & 1);
            asm volatile("cp.async.wait_group 1;" ::: "memory");
        } else {
            asm volatile("cp.async.wait_group 0;" ::: "memory");
        }
        __syncthreads();

        const uint32_t stg = sb + (it & 1) * STAGE_B;

        // ---- prologue: A frags for kk=0, B frags for step 0 ----
#pragma unroll
        for (int mi = 0; mi < 4; mi++) {
            const uint32_t ad = stg + (wm + mi * 16 + a_row) * TPITCH + a_kb;
            LDMX4(ah[0][mi], ad);
            LDMX4(al[0][mi], ad + GT_B);
        }
        {
            const uint32_t bd = stg + 2 * GT_B + (wn + b_row) * TPITCH + b_kb;
            LDMX4(bhf[0], bd);
            LDMX4(blf[0], bd + GT_B);
        }

        // ---- 8 pipelined steps: step s = (kk = s>>2, g = s&3) ----
#pragma unroll
        for (int s = 0; s < 8; s++) {
            const int kk  = s >> 2;
            const int g   = s & 3;
            const int buf = s & 1;
            // prefetch B for step s+1
            if (s < 7) {
                const int kk1 = (s + 1) >> 2, g1 = (s + 1) & 3;
                const uint32_t bd = stg + 2 * GT_B + (wn + g1 * 16 + b_row) * TPITCH + kk1 * 32 + b_kb;
                LDMX4(bhf[buf ^ 1], bd);
                LDMX4(blf[buf ^ 1], bd + GT_B);
            }
            // prefetch A for kk=1, one mi per step over steps 0..3
            if (s < 4) {
                const uint32_t ad = stg + (wm + s * 16 + a_row) * TPITCH + 32 + a_kb;
                LDMX4(ah[1][s], ad);
                LDMX4(al[1][s], ad + GT_B);
            }
            // MMAs: term-major so same-acc chains are spaced 8 apart
#pragma unroll
            for (int mi = 0; mi < 4; mi++)
#pragma unroll
                for (int nn = 0; nn < 2; nn++)
                    MMA16816(acc[mi][2 * g + nn], ah[kk][mi], &bhf[buf][2 * nn]);
#pragma unroll
            for (int mi = 0; mi < 4; mi++)
#pragma unroll
                for (int nn = 0; nn < 2; nn++)
                    MMA16816(acc[mi][2 * g + nn], ah[kk][mi], &blf[buf][2 * nn]);
#pragma unroll
            for (int mi = 0; mi < 4; mi++)
#pragma unroll
                for (int nn = 0; nn < 2; nn++)
                    MMA16816(acc[mi][2 * g + nn], al[kk][mi], &bhf[buf][2 * nn]);
        }
        __syncthreads();
    }

    const int r_in = lane >> 2;
    const int c_in = (lane & 3) * 2;
#pragma unroll
    for (int mi = 0; mi < 4; mi++)
#pragma unroll
        for (int ni = 0; ni < 8; ni++) {
            const int n = n0 + wn + ni * 8 + c_in;
            const float2 bz = *(const float2*)&bias[n];
#pragma unroll
            for (int half = 0; half < 2; half++) {
                const int m = m0 + wm + mi * 16 + r_in + half * 8;
                float vx = acc[mi][ni][half * 2 + 0] + bz.x;
                float vy = acc[mi][ni][half * 2 + 1] + bz.y;
                if (SCATTER) {
                    const int bb = m >> 9, t = m & 511, hh = n >> 6, d = n & 63;
                    const long idx = (((long)(bb * H_ + hh) * T_ + t) << 6) + d;
                    __nv_bfloat16 hx, lx, hy, ly;
                    bsplit(vx, hx, lx); bsplit(vy, hy, ly);
                    *(__nv_bfloat162*)&outhi[idx] = __nv_bfloat162(hx, hy);
                    *(__nv_bfloat162*)&outlo[idx] = __nv_bfloat162(lx, ly);
                } else {
                    float2 v; v.x = vx; v.y = vy;
                    *(float2*)&out[(long)m * C_ + n] = v;
                }
            }
        }
}

// =================================================================
// Tensor-core flash attention v2 (R14, unchanged): CTA = 64 queries,
// 128 threads, 2 CTAs/SM.
// =================================================================
#define AP       144                 // smem pitch bytes for 64 bf16 row
#define QT_B     (64 * AP)           // 9216 (one of hi/lo, 64 q rows)
#define KT_B     (64 * AP)           // 9216
#define STAGE_KV (4 * KT_B)          // Khi,Klo,Vhi,Vlo = 36864
#define SMEM_ATT (2 * QT_B + 2 * STAGE_KV)   // 92160 -> 2 CTAs/SM

__global__ __launch_bounds__(128, 2) void attn_tc(
    const __nv_bfloat16* __restrict__ qhi, const __nv_bfloat16* __restrict__ qlo,
    const __nv_bfloat16* __restrict__ khi, const __nv_bfloat16* __restrict__ klo,
    const __nv_bfloat16* __restrict__ vhi, const __nv_bfloat16* __restrict__ vlo,
    const float* __restrict__ rpb,
    __nv_bfloat16* __restrict__ outhi, __nv_bfloat16* __restrict__ outlo)
{
    extern __shared__ char smem[];
    const uint32_t sb  = smem_u32(smem);
    const uint32_t sKV = sb + 2 * QT_B;

    const int tid = threadIdx.x, lane = tid & 31, w = tid >> 5;   // w: 0..3
    const int qb = (T_ / 64 - 1) - blockIdx.x;   // heavy tiles first
    const int bh = blockIdx.y;
    const int h = bh & (H_ - 1), b = bh >> 4;
    const long base = (long)bh * T_ * D_;

    {
#pragma unroll
        for (int j = 0; j < 8; j++) {
            int idx = tid + j * 128;          // 0..1023
            int arr = idx >> 9;
            int pos = idx & 511;
            int r = pos >> 3, ch = pos & 7;
            const __nv_bfloat16* src = (arr ? qlo : qhi) + base + (long)(qb * 64 + r) * D_ + ch * 8;
            CP_ASYNC16(sb + arr * QT_B + r * AP + ch * 16, src);
        }
        CP_COMMIT();
    }

    auto load_kv = [&](int kb, int s) {
        const uint32_t dst = sKV + s * STAGE_KV;
        const __nv_bfloat16* srcs[4] = {
            khi + base + (long)kb * 64 * D_, klo + base + (long)kb * 64 * D_,
            vhi + base + (long)kb * 64 * D_, vlo + base + (long)kb * 64 * D_ };
#pragma unroll
        for (int j = 0; j < 16; j++) {
            int idx = tid + j * 128;          // 0..2047
            int sub = idx >> 9;
            int pos = idx & 511;
            int r = pos >> 3, ch = pos & 7;
            CP_ASYNC16(dst + sub * KT_B + r * AP + ch * 16, srcs[sub] + (long)r * D_ + ch * 8);
        }
        CP_COMMIT();
    };

    const int nkb = qb + 1;
    load_kv(0, 0);

    float m_1 = -1e30f, m_2 = -1e30f, l_1 = 0.0f, l_2 = 0.0f;
    float o[8][4];
#pragma unroll
    for (int j = 0; j < 8; j++)
#pragma unroll
        for (int r = 0; r < 4; r++) o[j][r] = 0.0f;

    const int r1  = lane >> 2;
    const int qg1 = qb * 64 + 16 * w + r1;
    const int qg2 = qg1 + 8;
    const int qmax = qb * 64 + 16 * w + 15;
    const float* bias_base = rpb + (long)h * T_ * T_;

    const int a_row = lane & 15;
    const int a_cb  = (lane >> 4) * 16;
    const int b_row = (lane & 7) + ((lane >> 4) << 3);
    const int b_cb  = ((lane >> 3) & 1) * 16;
    const int v_row = (lane & 7) + (((lane >> 3) & 1) << 3);
    const int v_cb  = (lane >> 4) * 16;

    for (int kb = 0; kb < nkb; kb++) {
        const int s = kb & 1;
        if (kb + 1 < nkb) {
            load_kv(kb + 1, s ^ 1);
            asm volatile("cp.async.wait_group 1;" ::: "memory");
        } else {
            asm volatile("cp.async.wait_group 0;" ::: "memory");
        }
        __syncthreads();

        const bool active = (kb * 64 <= qmax);
        if (active) {
            const uint32_t stK = sKV + s * STAGE_KV;
            const uint32_t stV = stK + 2 * KT_B;
            const int ng = min(4, ((qmax - kb * 64) >> 4) + 1);

            float sc[8][4];
#pragma unroll
            for (int j = 0; j < 8; j++)
#pragma unroll
                for (int r = 0; r < 4; r++) sc[j][r] = 0.0f;

#pragma unroll
            for (int kk = 0; kk < 4; kk++) {
                uint32_t ah[4], al[4];
                const uint32_t qa = sb + (16 * w + a_row) * AP + kk * 32 + a_cb;
                LDMX4(ah, qa);
                LDMX4(al, qa + QT_B);
                uint32_t bh8[8][2], bl8[8][2];
#pragma unroll
                for (int g = 0; g < 4; g++) {
                    if (g < ng) {
                        const uint32_t ba = stK + (g * 16 + b_row) * AP + kk * 32 + b_cb;
                        LDMX4(&bh8[2 * g][0], ba);
                        LDMX4(&bl8[2 * g][0], ba + KT_B);
                    }
                }
#pragma unroll
                for (int j = 0; j < 8; j++) {
                    if ((j >> 1) < ng) {
                        MMA16816(sc[j], ah, bh8[j]);
                        MMA16816(sc[j], ah, bl8[j]);
                        MMA16816(sc[j], al, bh8[j]);
                    }
                }
            }

            float mx1 = -1e30f, mx2 = -1e30f;
#pragma unroll
            for (int j = 0; j < 8; j++) {
                const int col = kb * 64 + 8 * j + 2 * (lane & 3);
                const float2 bb1 = *(const float2*)(bias_base + (long)qg1 * T_ + col);
                const float2 bb2 = *(const float2*)(bias_base + (long)qg2 * T_ + col);
                sc[j][0] = (col     > qg1) ? -1e30f : sc[j][0] * 0.125f + bb1.x;
                sc[j][1] = (col + 1 > qg1) ? -1e30f : sc[j][1] * 0.125f + bb1.y;
                sc[j][2] = (col     > qg2) ? -1e30f : sc[j][2] * 0.125f + bb2.x;
                sc[j][3] = (col + 1 > qg2) ? -1e30f : sc[j][3] * 0.125f + bb2.y;
                mx1 = fmaxf(mx1, fmaxf(sc[j][0], sc[j][1]));
                mx2 = fmaxf(mx2, fmaxf(sc[j][2], sc[j][3]));
            }
#pragma unroll
            for (int off = 1; off < 4; off <<= 1) {
                mx1 = fmaxf(mx1, __shfl_xor_sync(0xffffffffu, mx1, off));
                mx2 = fmaxf(mx2, __shfl_xor_sync(0xffffffffu, mx2, off));
            }
            const float mn1 = fmaxf(m_1, mx1), mn2 = fmaxf(m_2, mx2);
            const float c1 = __expf(m_1 - mn1), c2 = __expf(m_2 - mn2);
            m_1 = mn1; m_2 = mn2;
            float rs1 = 0.0f, rs2 = 0.0f;
#pragma unroll
            for (int j = 0; j < 8; j++) {
                sc[j][0] = __expf(sc[j][0] - mn1); rs1 += sc[j][0];
                sc[j][1] = __expf(sc[j][1] - mn1); rs1 += sc[j][1];
                sc[j][2] = __expf(sc[j][2] - mn2); rs2 += sc[j][2];
                sc[j][3] = __expf(sc[j][3] - mn2); rs2 += sc[j][3];
            }
#pragma unroll
            for (int off = 1; off < 4; off <<= 1) {
                rs1 += __shfl_xor_sync(0xffffffffu, rs1, off);
                rs2 += __shfl_xor_sync(0xffffffffu, rs2, off);
            }
            l_1 = l_1 * c1 + rs1;
            l_2 = l_2 * c2 + rs2;
#pragma unroll
            for (int j = 0; j < 8; j++) {
                o[j][0] *= c1; o[j][1] *= c1;
                o[j][2] *= c2; o[j][3] *= c2;
            }

#pragma unroll
            for (int ks = 0; ks < 4; ks++) {
                if (ks < ng) {
                    uint32_t ph[4], pl[4];
                    {
                        __nv_bfloat16 h0, l0, h1, l1;
#pragma unroll
                        for (int q = 0; q < 2; q++) {
                            const float* p = sc[2 * ks + q];
                            bsplit(p[0], h0, l0); bsplit(p[1], h1, l1);
                            ph[2 * q]     = packb2(h0, h1);
                            pl[2 * q]     = packb2(l0, l1);
                            bsplit(p[2], h0, l0); bsplit(p[3], h1, l1);
                            ph[2 * q + 1] = packb2(h0, h1);
                            pl[2 * q + 1] = packb2(l0, l1);
                        }
                    }
                    uint32_t vh8[8][2], vl8[8][2];
#pragma unroll
                    for (int g = 0; g < 4; g++) {
                        const uint32_t va = stV + (ks * 16 + v_row) * AP + g * 32 + v_cb;
                        LDMX4T(&vh8[2 * g][0], va);
                        LDMX4T(&vl8[2 * g][0], va + KT_B);
                    }
#pragma unroll
                    for (int j = 0; j < 8; j++) {
                        MMA16816(o[j], ph, vh8[j]);
                        MMA16816(o[j], ph, vl8[j]);
                        MMA16816(o[j], pl, vh8[j]);
                    }
                }
            }
        }
        __syncthreads();
    }

    // ---- epilogue ----
    const float inv1 = 1.0f / l_1;
    const float inv2 = 1.0f / l_2;
    const int t1 = qb * 64 + 16 * w + r1;
    const int d0 = 2 * (lane & 3);
#pragma unroll
    for (int j = 0; j < 8; j++) {
        const int d = 8 * j + d0;
        __nv_bfloat16 h0, l0, h1, l1;
        bsplit(o[j][0] * inv1, h0, l0);
        bsplit(o[j][1] * inv1, h1, l1);
        const long i1 = (long)(b * T_ + t1) * C_ + h * 64 + d;
        *(__nv_bfloat162*)&outhi[i1] = __nv_bfloat162(h0, h1);
        *(__nv_bfloat162*)&outlo[i1] = __nv_bfloat162(l0, l1);
        bsplit(o[j][2] * inv2, h0, l0);
        bsplit(o[j][3] * inv2, h1, l1);
        const long i2 = (long)(b * T_ + t1 + 8) * C_ + h * 64 + d;
        *(__nv_bfloat162*)&outhi[i2] = __nv_bfloat162(h0, h1);
        *(__nv_bfloat162*)&outlo[i2] = __nv_bfloat162(l0, l1);
    }
}

// =================================================================
extern "C" void kernel_launch(void* const* d_in, const int* in_sizes, int n_in,
                              void* d_out, int out_size)
{
    const float* x   = (const float*)d_in[0];
    const float* Wq  = (const float*)d_in[1];
    const float* bq  = (const float*)d_in[2];
    const float* Wk  = (const float*)d_in[3];
    const float* bk  = (const float*)d_in[4];
    const float* Wv  = (const float*)d_in[5];
    const float* bv  = (const float*)d_in[6];
    const float* Wo  = (const float*)d_in[7];
    const float* bo  = (const float*)d_in[8];
    const float* rpb = (const float*)d_in[9];
    float* out = (float*)d_out;

    __nv_bfloat16 *xhi, *xlo, *whi, *wlo;
    __nv_bfloat16 *qhi, *qlo, *khi, *klo, *vhi, *vlo, *ahi, *alo;
    cudaGetSymbolAddress((void**)&xhi, gx_hi);
    cudaGetSymbolAddress((void**)&xlo, gx_lo);
    cudaGetSymbolAddress((void**)&whi, gw_hi);
    cudaGetSymbolAddress((void**)&wlo, gw_lo);
    cudaGetSymbolAddress((void**)&qhi, gq_hi);
    cudaGetSymbolAddress((void**)&qlo, gq_lo);
    cudaGetSymbolAddress((void**)&khi, gk_hi);
    cudaGetSymbolAddress((void**)&klo, gk_lo);
    cudaGetSymbolAddress((void**)&vhi, gv_hi);
    cudaGetSymbolAddress((void**)&vlo, gv_lo);
    cudaGetSymbolAddress((void**)&ahi, ga_hi);
    cudaGetSymbolAddress((void**)&alo, ga_lo);

    cudaFuncSetAttribute(gemm_big<1>,
                         cudaFuncAttributeMaxDynamicSharedMemorySize, GEMM_SMEM);
    cudaFuncSetAttribute(gemm_big<0>,
                         cudaFuncAttributeMaxDynamicSharedMemorySize, GEMM_SMEM);
    cudaFuncSetAttribute(attn_tc,
                         cudaFuncAttributeMaxDynamicSharedMemorySize, SMEM_ATT);

    const int WW = C_ * C_;
    split_kernel<<<(M_ * K_) / 1024, 256>>>(x, xhi, xlo);
    split_w_kernel<<<dim3(WW / 1024, 4), 256>>>(Wq, Wk, Wv, Wo, whi, wlo);

    gemm_big<1><<<dim3(C_ / 128, M_ / 128, 3), 128, GEMM_SMEM>>>(
        xhi, xlo, whi, wlo, bq, bk, bv, nullptr,
        qhi, qlo, khi, klo, vhi, vlo);

    attn_tc<<<dim3(T_ / 64, B_ * H_), 128, SMEM_ATT>>>(
        qhi, qlo, khi, klo, vhi, vlo, rpb, ahi, alo);

    gemm_big<0><<<dim3(C_ / 128, M_ / 128, 1), 128, GEMM_SMEM>>>(
        ahi, alo, whi + 3L * WW, wlo + 3L * WW, bo, bo, bo, out,
        nullptr, nullptr, nullptr, nullptr, nullptr, nullptr);
}

// round 16
// speedup vs baseline: 1.0432x; 1.0432x over previous
#include <cuda_runtime.h>
#include <cuda_bf16.h>
#include <cstdint>
#include <math.h>

#define B_   16
#define T_   512
#define C_   1024
#define H_   16
#define D_   64
#define M_   (B_ * T_)      // 8192
#define K_   C_             // 1024

// ---------------- scratch (no allocations allowed) ----------------
__device__ __nv_bfloat16 gx_hi[M_ * K_];
__device__ __nv_bfloat16 gx_lo[M_ * K_];
__device__ __nv_bfloat16 gw_hi[4 * C_ * C_];   // q,k,v,o
__device__ __nv_bfloat16 gw_lo[4 * C_ * C_];
__device__ __nv_bfloat16 gq_hi[M_ * C_];       // (B,H,T,D)
__device__ __nv_bfloat16 gq_lo[M_ * C_];
__device__ __nv_bfloat16 gk_hi[M_ * C_];
__device__ __nv_bfloat16 gk_lo[M_ * C_];
__device__ __nv_bfloat16 gv_hi[M_ * C_];
__device__ __nv_bfloat16 gv_lo[M_ * C_];
__device__ __nv_bfloat16 ga_hi[M_ * C_];       // (B,T,C) attn out
__device__ __nv_bfloat16 ga_lo[M_ * C_];

// ================= helpers =================
__device__ __forceinline__ uint32_t smem_u32(const void* p) {
    return (uint32_t)__cvta_generic_to_shared(p);
}

#define CP_ASYNC16(dst, src) \
    asm volatile("cp.async.cg.shared.global [%0], [%1], 16;" :: "r"(dst), "l"(src) : "memory")
#define CP_COMMIT() asm volatile("cp.async.commit_group;" ::: "memory")

#define LDMX4(r, addr) \
    asm volatile("ldmatrix.sync.aligned.m8n8.x4.shared.b16 {%0,%1,%2,%3}, [%4];" \
        : "=r"((r)[0]), "=r"((r)[1]), "=r"((r)[2]), "=r"((r)[3]) : "r"(addr))

#define LDMX4T(r, addr) \
    asm volatile("ldmatrix.sync.aligned.m8n8.x4.trans.shared.b16 {%0,%1,%2,%3}, [%4];" \
        : "=r"((r)[0]), "=r"((r)[1]), "=r"((r)[2]), "=r"((r)[3]) : "r"(addr))

#define MMA16816(d, a, b) \
    asm volatile("mma.sync.aligned.m16n8k16.row.col.f32.bf16.bf16.f32 " \
        "{%0,%1,%2,%3}, {%4,%5,%6,%7}, {%8,%9}, {%0,%1,%2,%3};" \
        : "+f"((d)[0]), "+f"((d)[1]), "+f"((d)[2]), "+f"((d)[3]) \
        : "r"((a)[0]), "r"((a)[1]), "r"((a)[2]), "r"((a)[3]), \
          "r"((b)[0]), "r"((b)[1]))

__device__ __forceinline__ void bsplit(float x, __nv_bfloat16& h, __nv_bfloat16& l) {
    h = __float2bfloat16(x);
    l = __float2bfloat16(x - __bfloat162float(h));
}
__device__ __forceinline__ uint32_t packb2(__nv_bfloat16 a, __nv_bfloat16 b) {
    __nv_bfloat162 t(a, b);
    return *(uint32_t*)&t;
}

// =================================================================
// fused split: fp32 -> (hi bf16, lo bf16), x + all 4 weights in one
// launch. grid = (1024, 12): y<8 -> x chunk y; y>=8 -> weight y-8.
// =================================================================
__device__ __forceinline__ void do_split(
    const float* __restrict__ in, __nv_bfloat16* __restrict__ hi,
    __nv_bfloat16* __restrict__ lo, int i)
{
    float4 v = ((const float4*)in)[i];
    __nv_bfloat16 h0, h1, h2, h3, l0, l1, l2, l3;
    bsplit(v.x, h0, l0); bsplit(v.y, h1, l1);
    bsplit(v.z, h2, l2); bsplit(v.w, h3, l3);
    ((__nv_bfloat162*)hi)[2 * i + 0] = __nv_bfloat162(h0, h1);
    ((__nv_bfloat162*)hi)[2 * i + 1] = __nv_bfloat162(h2, h3);
    ((__nv_bfloat162*)lo)[2 * i + 0] = __nv_bfloat162(l0, l1);
    ((__nv_bfloat162*)lo)[2 * i + 1] = __nv_bfloat162(l2, l3);
}

__global__ __launch_bounds__(256) void split_all_kernel(
    const float* __restrict__ x,
    const float* __restrict__ w0, const float* __restrict__ w1,
    const float* __restrict__ w2, const float* __restrict__ w3,
    __nv_bfloat16* __restrict__ xhi, __nv_bfloat16* __restrict__ xlo,
    __nv_bfloat16* __restrict__ whi, __nv_bfloat16* __restrict__ wlo)
{
    const int y = blockIdx.y;
    const int WW = C_ * C_;
    if (y < 8) {
        // x chunk y: 1024 blocks x 256 threads x 4 floats = 1M floats/chunk
        do_split(x, xhi, xlo, ((y << 10) + blockIdx.x) * 256 + threadIdx.x);
    } else {
        const int wsel = y - 8;
        const float* in = (wsel == 0) ? w0 : (wsel == 1) ? w1 : (wsel == 2) ? w2 : w3;
        do_split(in, whi + wsel * WW, wlo + wsel * WW,
                 blockIdx.x * 256 + threadIdx.x);
    }
}

// =================================================================
// mma.sync bf16x3 GEMM (R13/R14 proven config): CTA 128x128, 4 warps
// (64x64 warp tile), 2-stage cp.async, 2 CTAs/SM.
// SCATTER=1: z selects W/bias/out (fused QKV).
// =================================================================
#define NITER    32               // K / 32
#define TPITCH   80               // bytes per 32-bf16 row (64 + 16 pad)
#define GT_B     (128 * TPITCH)   // 10240 (one tile: 128 rows)
#define STAGE_B  (4 * GT_B)       // Ahi,Alo,Bhi,Blo = 40960
#define GEMM_SMEM (2 * STAGE_B)   // 81920 -> 2 CTAs/SM

template<int SCATTER>
__global__ __launch_bounds__(128, 2) void gemm_big(
    const __nv_bfloat16* __restrict__ Ahi, const __nv_bfloat16* __restrict__ Alo,
    const __nv_bfloat16* __restrict__ Whi, const __nv_bfloat16* __restrict__ Wlo,
    const float* __restrict__ b0, const float* __restrict__ b1,
    const float* __restrict__ b2, float* __restrict__ out,
    __nv_bfloat16* __restrict__ oh0, __nv_bfloat16* __restrict__ ol0,
    __nv_bfloat16* __restrict__ oh1, __nv_bfloat16* __restrict__ ol1,
    __nv_bfloat16* __restrict__ oh2, __nv_bfloat16* __restrict__ ol2)
{
    extern __shared__ char smem[];
    const uint32_t sb = smem_u32(smem);
    const int tid  = threadIdx.x;
    const int lane = tid & 31;
    const int warp = tid >> 5;          // 0..3
    const int m0 = blockIdx.y * 128;
    const int n0 = blockIdx.x * 128;
    const int wm = (warp & 1) * 64;
    const int wn = (warp >> 1) * 64;

    const int z = SCATTER ? blockIdx.z : 0;
    const long WW = (long)C_ * C_;
    const __nv_bfloat16* Bh = Whi + z * WW;
    const __nv_bfloat16* Bl = Wlo + z * WW;
    const float* bias = (z == 0) ? b0 : (z == 1) ? b1 : b2;
    __nv_bfloat16* outhi = (z == 0) ? oh0 : (z == 1) ? oh1 : oh2;
    __nv_bfloat16* outlo = (z == 0) ? ol0 : (z == 1) ? ol1 : ol2;

    const __nv_bfloat16* bases[4] = {
        Ahi + (long)m0 * K_, Alo + (long)m0 * K_,
        Bh + (long)n0 * K_, Bl + (long)n0 * K_ };

    auto load_stage = [&](int it, int s) {
        const int k0 = it * 32;
        const uint32_t sdst = sb + s * STAGE_B;
#pragma unroll
        for (int j = 0; j < 16; j++) {
            const int idx = tid + j * 128;
            const int tile = idx >> 9;
            const int pos = idx & 511;
            const int row = pos >> 2;
            const int ch  = pos & 3;
            const __nv_bfloat16* src = bases[tile] + (long)row * K_ + k0 + ch * 8;
            CP_ASYNC16(sdst + tile * GT_B + row * TPITCH + ch * 16, src);
        }
        CP_COMMIT();
    };

    float acc[4][8][4];
#pragma unroll
    for (int mi = 0; mi < 4; mi++)
#pragma unroll
        for (int ni = 0; ni < 8; ni++)
#pragma unroll
            for (int r = 0; r < 4; r++) acc[mi][ni][r] = 0.0f;

    load_stage(0, 0);

    const int a_row = lane & 15;
    const int a_kb  = (lane >> 4) * 16;
    const int b_row = (lane & 7) + ((lane >> 4) << 3);
    const int b_kb  = ((lane >> 3) & 1) * 16;

    for (int it = 0; it < NITER; it++) {
        if (it + 1 < NITER) {
            load_stage(it + 1, (it + 1) & 1);
            asm volatile("cp.async.wait_group 1;" ::: "memory");
        } else {
            asm volatile("cp.async.wait_group 0;" ::: "memory");
        }
        __syncthreads();

        const uint32_t stg = sb + (it & 1) * STAGE_B;

#pragma unroll
        for (int kk = 0; kk < 2; kk++) {
            uint32_t ah[4][4], al[4][4];
#pragma unroll
            for (int mi = 0; mi < 4; mi++) {
                const uint32_t ad = stg + (wm + mi * 16 + a_row) * TPITCH + kk * 32 + a_kb;
                LDMX4(ah[mi], ad);
                LDMX4(al[mi], ad + GT_B);
            }
#pragma unroll
            for (int g = 0; g < 4; g++) {
                uint32_t bh[2][2], bl[2][2];
                const uint32_t bd = stg + 2 * GT_B + (wn + g * 16 + b_row) * TPITCH + kk * 32 + b_kb;
                LDMX4(&bh[0][0], bd);
                LDMX4(&bl[0][0], bd + GT_B);
#pragma unroll
                for (int mi = 0; mi < 4; mi++)
#pragma unroll
                    for (int nn = 0; nn < 2; nn++) {
                        MMA16816(acc[mi][2 * g + nn], ah[mi], bh[nn]);
                        MMA16816(acc[mi][2 * g + nn], ah[mi], bl[nn]);
                        MMA16816(acc[mi][2 * g + nn], al[mi], bh[nn]);
                    }
            }
        }
        __syncthreads();
    }

    const int r_in = lane >> 2;
    const int c_in = (lane & 3) * 2;
#pragma unroll
    for (int mi = 0; mi < 4; mi++)
#pragma unroll
        for (int ni = 0; ni < 8; ni++) {
            const int n = n0 + wn + ni * 8 + c_in;
            const float2 bz = *(const float2*)&bias[n];
#pragma unroll
            for (int half = 0; half < 2; half++) {
                const int m = m0 + wm + mi * 16 + r_in + half * 8;
                float vx = acc[mi][ni][half * 2 + 0] + bz.x;
                float vy = acc[mi][ni][half * 2 + 1] + bz.y;
                if (SCATTER) {
                    const int bb = m >> 9, t = m & 511, hh = n >> 6, d = n & 63;
                    const long idx = (((long)(bb * H_ + hh) * T_ + t) << 6) + d;
                    __nv_bfloat16 hx, lx, hy, ly;
                    bsplit(vx, hx, lx); bsplit(vy, hy, ly);
                    *(__nv_bfloat162*)&outhi[idx] = __nv_bfloat162(hx, hy);
                    *(__nv_bfloat162*)&outlo[idx] = __nv_bfloat162(lx, ly);
                } else {
                    float2 v; v.x = vx; v.y = vy;
                    *(float2*)&out[(long)m * C_ + n] = v;
                }
            }
        }
}

// =================================================================
// Tensor-core flash attention v2 (R14, unchanged): CTA = 64 queries,
// 128 threads, 2 CTAs/SM, heavy tiles first.
// =================================================================
#define AP       144                 // smem pitch bytes for 64 bf16 row
#define QT_B     (64 * AP)           // 9216 (one of hi/lo, 64 q rows)
#define KT_B     (64 * AP)           // 9216
#define STAGE_KV (4 * KT_B)          // Khi,Klo,Vhi,Vlo = 36864
#define SMEM_ATT (2 * QT_B + 2 * STAGE_KV)   // 92160 -> 2 CTAs/SM

__global__ __launch_bounds__(128, 2) void attn_tc(
    const __nv_bfloat16* __restrict__ qhi, const __nv_bfloat16* __restrict__ qlo,
    const __nv_bfloat16* __restrict__ khi, const __nv_bfloat16* __restrict__ klo,
    const __nv_bfloat16* __restrict__ vhi, const __nv_bfloat16* __restrict__ vlo,
    const float* __restrict__ rpb,
    __nv_bfloat16* __restrict__ outhi, __nv_bfloat16* __restrict__ outlo)
{
    extern __shared__ char smem[];
    const uint32_t sb  = smem_u32(smem);
    const uint32_t sKV = sb + 2 * QT_B;

    const int tid = threadIdx.x, lane = tid & 31, w = tid >> 5;   // w: 0..3
    const int qb = (T_ / 64 - 1) - blockIdx.x;   // heavy tiles first
    const int bh = blockIdx.y;
    const int h = bh & (H_ - 1), b = bh >> 4;
    const long base = (long)bh * T_ * D_;

    {
#pragma unroll
        for (int j = 0; j < 8; j++) {
            int idx = tid + j * 128;          // 0..1023
            int arr = idx >> 9;
            int pos = idx & 511;
            int r = pos >> 3, ch = pos & 7;
            const __nv_bfloat16* src = (arr ? qlo : qhi) + base + (long)(qb * 64 + r) * D_ + ch * 8;
            CP_ASYNC16(sb + arr * QT_B + r * AP + ch * 16, src);
        }
        CP_COMMIT();
    }

    auto load_kv = [&](int kb, int s) {
        const uint32_t dst = sKV + s * STAGE_KV;
        const __nv_bfloat16* srcs[4] = {
            khi + base + (long)kb * 64 * D_, klo + base + (long)kb * 64 * D_,
            vhi + base + (long)kb * 64 * D_, vlo + base + (long)kb * 64 * D_ };
#pragma unroll
        for (int j = 0; j < 16; j++) {
            int idx = tid + j * 128;          // 0..2047
            int sub = idx >> 9;
            int pos = idx & 511;
            int r = pos >> 3, ch = pos & 7;
            CP_ASYNC16(dst + sub * KT_B + r * AP + ch * 16, srcs[sub] + (long)r * D_ + ch * 8);
        }
        CP_COMMIT();
    };

    const int nkb = qb + 1;
    load_kv(0, 0);

    float m_1 = -1e30f, m_2 = -1e30f, l_1 = 0.0f, l_2 = 0.0f;
    float o[8][4];
#pragma unroll
    for (int j = 0; j < 8; j++)
#pragma unroll
        for (int r = 0; r < 4; r++) o[j][r] = 0.0f;

    const int r1  = lane >> 2;
    const int qg1 = qb * 64 + 16 * w + r1;
    const int qg2 = qg1 + 8;
    const int qmax = qb * 64 + 16 * w + 15;
    const float* bias_base = rpb + (long)h * T_ * T_;

    const int a_row = lane & 15;
    const int a_cb  = (lane >> 4) * 16;
    const int b_row = (lane & 7) + ((lane >> 4) << 3);
    const int b_cb  = ((lane >> 3) & 1) * 16;
    const int v_row = (lane & 7) + (((lane >> 3) & 1) << 3);
    const int v_cb  = (lane >> 4) * 16;

    for (int kb = 0; kb < nkb; kb++) {
        const int s = kb & 1;
        if (kb + 1 < nkb) {
            load_kv(kb + 1, s ^ 1);
            asm volatile("cp.async.wait_group 1;" ::: "memory");
        } else {
            asm volatile("cp.async.wait_group 0;" ::: "memory");
        }
        __syncthreads();

        const bool active = (kb * 64 <= qmax);
        if (active) {
            const uint32_t stK = sKV + s * STAGE_KV;
            const uint32_t stV = stK + 2 * KT_B;
            const int ng = min(4, ((qmax - kb * 64) >> 4) + 1);

            float sc[8][4];
#pragma unroll
            for (int j = 0; j < 8; j++)
#pragma unroll
                for (int r = 0; r < 4; r++) sc[j][r] = 0.0f;

#pragma unroll
            for (int kk = 0; kk < 4; kk++) {
                uint32_t ah[4], al[4];
                const uint32_t qa = sb + (16 * w + a_row) * AP + kk * 32 + a_cb;
                LDMX4(ah, qa);
                LDMX4(al, qa + QT_B);
                uint32_t bh8[8][2], bl8[8][2];
#pragma unroll
                for (int g = 0; g < 4; g++) {
                    if (g < ng) {
                        const uint32_t ba = stK + (g * 16 + b_row) * AP + kk * 32 + b_cb;
                        LDMX4(&bh8[2 * g][0], ba);
                        LDMX4(&bl8[2 * g][0], ba + KT_B);
                    }
                }
#pragma unroll
                for (int j = 0; j < 8; j++) {
                    if ((j >> 1) < ng) {
                        MMA16816(sc[j], ah, bh8[j]);
                        MMA16816(sc[j], ah, bl8[j]);
                        MMA16816(sc[j], al, bh8[j]);
                    }
                }
            }

            float mx1 = -1e30f, mx2 = -1e30f;
#pragma unroll
            for (int j = 0; j < 8; j++) {
                const int col = kb * 64 + 8 * j + 2 * (lane & 3);
                const float2 bb1 = *(const float2*)(bias_base + (long)qg1 * T_ + col);
                const float2 bb2 = *(const float2*)(bias_base + (long)qg2 * T_ + col);
                sc[j][0] = (col     > qg1) ? -1e30f : sc[j][0] * 0.125f + bb1.x;
                sc[j][1] = (col + 1 > qg1) ? -1e30f : sc[j][1] * 0.125f + bb1.y;
                sc[j][2] = (col     > qg2) ? -1e30f : sc[j][2] * 0.125f + bb2.x;
                sc[j][3] = (col + 1 > qg2) ? -1e30f : sc[j][3] * 0.125f + bb2.y;
                mx1 = fmaxf(mx1, fmaxf(sc[j][0], sc[j][1]));
                mx2 = fmaxf(mx2, fmaxf(sc[j][2], sc[j][3]));
            }
#pragma unroll
            for (int off = 1; off < 4; off <<= 1) {
                mx1 = fmaxf(mx1, __shfl_xor_sync(0xffffffffu, mx1, off));
                mx2 = fmaxf(mx2, __shfl_xor_sync(0xffffffffu, mx2, off));
            }
            const float mn1 = fmaxf(m_1, mx1), mn2 = fmaxf(m_2, mx2);
            const float c1 = __expf(m_1 - mn1), c2 = __expf(m_2 - mn2);
            m_1 = mn1; m_2 = mn2;
            float rs1 = 0.0f, rs2 = 0.0f;
#pragma unroll
            for (int j = 0; j < 8; j++) {
                sc[j][0] = __expf(sc[j][0] - mn1); rs1 += sc[j][0];
                sc[j][1] = __expf(sc[j][1] - mn1); rs1 += sc[j][1];
                sc[j][2] = __expf(sc[j][2] - mn2); rs2 += sc[j][2];
                sc[j][3] = __expf(sc[j][3] - mn2); rs2 += sc[j][3];
            }
#pragma unroll
            for (int off = 1; off < 4; off <<= 1) {
                rs1 += __shfl_xor_sync(0xffffffffu, rs1, off);
                rs2 += __shfl_xor_sync(0xffffffffu, rs2, off);
            }
            l_1 = l_1 * c1 + rs1;
            l_2 = l_2 * c2 + rs2;
#pragma unroll
            for (int j = 0; j < 8; j++) {
                o[j][0] *= c1; o[j][1] *= c1;
                o[j][2] *= c2; o[j][3] *= c2;
            }

#pragma unroll
            for (int ks = 0; ks < 4; ks++) {
                if (ks < ng) {
                    uint32_t ph[4], pl[4];
                    {
                        __nv_bfloat16 h0, l0, h1, l1;
#pragma unroll
                        for (int q = 0; q < 2; q++) {
                            const float* p = sc[2 * ks + q];
                            bsplit(p[0], h0, l0); bsplit(p[1], h1, l1);
                            ph[2 * q]     = packb2(h0, h1);
                            pl[2 * q]     = packb2(l0, l1);
                            bsplit(p[2], h0, l0); bsplit(p[3], h1, l1);
                            ph[2 * q + 1] = packb2(h0, h1);
                            pl[2 * q + 1] = packb2(l0, l1);
                        }
                    }
                    uint32_t vh8[8][2], vl8[8][2];
#pragma unroll
                    for (int g = 0; g < 4; g++) {
                        const uint32_t va = stV + (ks * 16 + v_row) * AP + g * 32 + v_cb;
                        LDMX4T(&vh8[2 * g][0], va);
                        LDMX4T(&vl8[2 * g][0], va + KT_B);
                    }
#pragma unroll
                    for (int j = 0; j < 8; j++) {
                        MMA16816(o[j], ph, vh8[j]);
                        MMA16816(o[j], ph, vl8[j]);
                        MMA16816(o[j], pl, vh8[j]);
                    }
                }
            }
        }
        __syncthreads();
    }

    // ---- epilogue ----
    const float inv1 = 1.0f / l_1;
    const float inv2 = 1.0f / l_2;
    const int t1 = qb * 64 + 16 * w + r1;
    const int d0 = 2 * (lane & 3);
#pragma unroll
    for (int j = 0; j < 8; j++) {
        const int d = 8 * j + d0;
        __nv_bfloat16 h0, l0, h1, l1;
        bsplit(o[j][0] * inv1, h0, l0);
        bsplit(o[j][1] * inv1, h1, l1);
        const long i1 = (long)(b * T_ + t1) * C_ + h * 64 + d;
        *(__nv_bfloat162*)&outhi[i1] = __nv_bfloat162(h0, h1);
        *(__nv_bfloat162*)&outlo[i1] = __nv_bfloat162(l0, l1);
        bsplit(o[j][2] * inv2, h0, l0);
        bsplit(o[j][3] * inv2, h1, l1);
        const long i2 = (long)(b * T_ + t1 + 8) * C_ + h * 64 + d;
        *(__nv_bfloat162*)&outhi[i2] = __nv_bfloat162(h0, h1);
        *(__nv_bfloat162*)&outlo[i2] = __nv_bfloat162(l0, l1);
    }
}

// =================================================================
extern "C" void kernel_launch(void* const* d_in, const int* in_sizes, int n_in,
                              void* d_out, int out_size)
{
    const float* x   = (const float*)d_in[0];
    const float* Wq  = (const float*)d_in[1];
    const float* bq  = (const float*)d_in[2];
    const float* Wk  = (const float*)d_in[3];
    const float* bk  = (const float*)d_in[4];
    const float* Wv  = (const float*)d_in[5];
    const float* bv  = (const float*)d_in[6];
    const float* Wo  = (const float*)d_in[7];
    const float* bo  = (const float*)d_in[8];
    const float* rpb = (const float*)d_in[9];
    float* out = (float*)d_out;

    __nv_bfloat16 *xhi, *xlo, *whi, *wlo;
    __nv_bfloat16 *qhi, *qlo, *khi, *klo, *vhi, *vlo, *ahi, *alo;
    cudaGetSymbolAddress((void**)&xhi, gx_hi);
    cudaGetSymbolAddress((void**)&xlo, gx_lo);
    cudaGetSymbolAddress((void**)&whi, gw_hi);
    cudaGetSymbolAddress((void**)&wlo, gw_lo);
    cudaGetSymbolAddress((void**)&qhi, gq_hi);
    cudaGetSymbolAddress((void**)&qlo, gq_lo);
    cudaGetSymbolAddress((void**)&khi, gk_hi);
    cudaGetSymbolAddress((void**)&klo, gk_lo);
    cudaGetSymbolAddress((void**)&vhi, gv_hi);
    cudaGetSymbolAddress((void**)&vlo, gv_lo);
    cudaGetSymbolAddress((void**)&ahi, ga_hi);
    cudaGetSymbolAddress((void**)&alo, ga_lo);

    cudaFuncSetAttribute(gemm_big<1>,
                         cudaFuncAttributeMaxDynamicSharedMemorySize, GEMM_SMEM);
    cudaFuncSetAttribute(gemm_big<0>,
                         cudaFuncAttributeMaxDynamicSharedMemorySize, GEMM_SMEM);
    cudaFuncSetAttribute(attn_tc,
                         cudaFuncAttributeMaxDynamicSharedMemorySize, SMEM_ATT);

    const int WW = C_ * C_;
    // one fused split launch: x (8 chunks) + 4 weights
    split_all_kernel<<<dim3(1024, 12), 256>>>(x, Wq, Wk, Wv, Wo,
                                              xhi, xlo, whi, wlo);

    gemm_big<1><<<dim3(C_ / 128, M_ / 128, 3), 128, GEMM_SMEM>>>(
        xhi, xlo, whi, wlo, bq, bk, bv, nullptr,
        qhi, qlo, khi, klo, vhi, vlo);

    attn_tc<<<dim3(T_ / 64, B_ * H_), 128, SMEM_ATT>>>(
        qhi, qlo, khi, klo, vhi, vlo, rpb, ahi, alo);

    gemm_big<0><<<dim3(C_ / 128, M_ / 128, 1), 128, GEMM_SMEM>>>(
        ahi, alo, whi + 3L * WW, wlo + 3L * WW, bo, bo, bo, out,
        nullptr, nullptr, nullptr, nullptr, nullptr, nullptr);
}